// round 13
// baseline (speedup 1.0000x reference)
#include <cuda_runtime.h>
#include <cuda_bf16.h>
#include <cstdint>

// ChamferDistance: dense all-pairs NN via packed f32x2 FMA.
// d(q,r) = ||q||^2 + dot4((qx,qy,qz,1), (-2rx,-2ry,-2rz,||r||^2))
// QPT=4 queries/thread, SPLITS=16 ref slabs (min-combined in reduce).
// Register double-buffered smem reads; launch_bounds(128,6) for reg headroom.

#define BATCH    16
#define NPTS     4096
#define DIRS     2
#define THREADS  128
#define QPT      4                        // queries per thread
#define QBLK     (THREADS * QPT)          // 512 queries per block
#define QTILES   (NPTS / QBLK)            // 8
#define SPLITS   16                       // ref slabs
#define RTILE    (NPTS / SPLITS)          // 256 refs per block
#define RPAIRS   (RTILE / 2)              // 128 packed pairs (4 KB smem)
#define TOTQ     (DIRS * BATCH * NPTS)    // 131072
#define R1BLOCKS 512
#define FINF     __int_as_float(0x7f800000)

__device__ float g_part[SPLITS][TOTQ];    // per-slab partial NN sq-dists (8 MB)
__device__ float g_bsum[R1BLOCKS];

// ---------- packed f32x2 helpers ----------
__device__ __forceinline__ unsigned long long ffma2(unsigned long long a,
                                                    unsigned long long b,
                                                    unsigned long long c) {
    unsigned long long d;
    asm("fma.rn.f32x2 %0, %1, %2, %3;" : "=l"(d) : "l"(a), "l"(b), "l"(c));
    return d;
}
__device__ __forceinline__ unsigned long long pack2(float lo, float hi) {
    unsigned long long d;
    asm("mov.b64 %0, {%1, %2};" : "=l"(d) : "r"(__float_as_uint(lo)), "r"(__float_as_uint(hi)));
    return d;
}
__device__ __forceinline__ void unpack2(unsigned long long v, float& lo, float& hi) {
    unsigned int l, h;
    asm("mov.b64 {%0, %1}, %2;" : "=r"(l), "=r"(h) : "l"(v));
    lo = __uint_as_float(l);
    hi = __uint_as_float(h);
}

// ---------------- main: dense slab scan ---------------------------------------
__global__ __launch_bounds__(THREADS, 6)
void chamfer_main_kernel(const float* __restrict__ x,
                         const float* __restrict__ y) {
    __shared__ float4 shA[RPAIRS];   // (-2x0,-2x1,-2y0,-2y1)
    __shared__ float4 shB[RPAIRS];   // (-2z0,-2z1, n0,  n1)

    const int qt  = blockIdx.x >> 4;          // query tile [0,8)
    const int s   = blockIdx.x & 15;          // ref slab  [0,16)
    const int b   = blockIdx.y;
    const int dir = blockIdx.z;

    const float* q = (dir == 0) ? x : y;
    const float* r = (dir == 0) ? y : x;
    const float* rbase = r + ((size_t)b * NPTS + s * RTILE) * 3;
    const int tid = threadIdx.x;

    // Load + transform slab refs (1 pair per thread).
    if (tid < RPAIRS) {
        const float* rp = rbase + (size_t)(2 * tid) * 3;
        float a0 = rp[0], a1 = rp[1], a2 = rp[2];
        float b0 = rp[3], b1 = rp[4], b2 = rp[5];
        float na = fmaf(a0, a0, fmaf(a1, a1, a2 * a2));
        float nb = fmaf(b0, b0, fmaf(b1, b1, b2 * b2));
        shA[tid] = make_float4(-2.0f * a0, -2.0f * b0, -2.0f * a1, -2.0f * b1);
        shB[tid] = make_float4(-2.0f * a2, -2.0f * b2, na, nb);
    }

    // Query registers (QPT=4).
    unsigned long long qx2[QPT], qy2[QPT], qz2[QPT];
    float q2[QPT];
    #pragma unroll
    for (int k = 0; k < QPT; k++) {
        int qi = qt * QBLK + k * THREADS + tid;
        const float* qp = q + ((size_t)b * NPTS + qi) * 3;
        float a = qp[0], c = qp[1], d = qp[2];
        qx2[k] = pack2(a, a);
        qy2[k] = pack2(c, c);
        qz2[k] = pack2(d, d);
        q2[k] = fmaf(a, a, fmaf(c, c, d * d));
    }

    __syncthreads();

    float mlo[QPT], mhi[QPT];
    #pragma unroll
    for (int k = 0; k < QPT; k++) { mlo[k] = FINF; mhi[k] = FINF; }

    const ulonglong2* __restrict__ A64 = reinterpret_cast<const ulonglong2*>(shA);
    const ulonglong2* __restrict__ B64 = reinterpret_cast<const ulonglong2*>(shB);

    // Register double-buffer: loads for j+1 issue before computing j.
    ulonglong2 va = A64[0];
    ulonglong2 vb = B64[0];
    #pragma unroll 4
    for (int j = 0; j < RPAIRS; j++) {
        const int jn = (j + 1) & (RPAIRS - 1);
        ulonglong2 nva = A64[jn];
        ulonglong2 nvb = B64[jn];
        #pragma unroll
        for (int k = 0; k < QPT; k++) {
            unsigned long long t =
                ffma2(qx2[k], va.x, ffma2(qy2[k], va.y, ffma2(qz2[k], vb.x, vb.y)));
            float tl, th;
            unpack2(t, tl, th);
            mlo[k] = fminf(mlo[k], tl);
            mhi[k] = fminf(mhi[k], th);
        }
        va = nva;
        vb = nvb;
    }

    // Plain store of per-slab partial (no atomics, no init).
    #pragma unroll
    for (int k = 0; k < QPT; k++) {
        int qi = qt * QBLK + k * THREADS + tid;
        g_part[s][(size_t)dir * BATCH * NPTS + (size_t)b * NPTS + qi] =
            q2[k] + fminf(mlo[k], mhi[k]);
    }
}

// ---------------- stage 2: min over slabs + block sums (vectorized) -----------
__global__ __launch_bounds__(256)
void chamfer_reduce1_kernel() {
    __shared__ float ws[8];
    float s = 0.f;
    for (int i = blockIdx.x * 256 + threadIdx.x; i < TOTQ / 4; i += R1BLOCKS * 256) {
        const float4* p0 = (const float4*)&g_part[0][0];
        float4 m = p0[i];
        #pragma unroll
        for (int p = 1; p < SPLITS; p++) {
            float4 v = ((const float4*)&g_part[p][0])[i];
            m.x = fminf(m.x, v.x);
            m.y = fminf(m.y, v.y);
            m.z = fminf(m.z, v.z);
            m.w = fminf(m.w, v.w);
        }
        s += (m.x + m.y) + (m.z + m.w);
    }
    #pragma unroll
    for (int o = 16; o; o >>= 1) s += __shfl_xor_sync(0xFFFFFFFFu, s, o);
    int lane = threadIdx.x & 31, wid = threadIdx.x >> 5;
    if (lane == 0) ws[wid] = s;
    __syncthreads();
    if (threadIdx.x == 0) {
        float v = 0.f;
        #pragma unroll
        for (int i = 0; i < 8; i++) v += ws[i];
        g_bsum[blockIdx.x] = v;
    }
}

// ---------------- stage 3: final sum ------------------------------------------
__global__ __launch_bounds__(512)
void chamfer_reduce2_kernel(float* __restrict__ out) {
    __shared__ float ws[16];
    float s = (threadIdx.x < R1BLOCKS) ? g_bsum[threadIdx.x] : 0.f;
    #pragma unroll
    for (int o = 16; o; o >>= 1) s += __shfl_xor_sync(0xFFFFFFFFu, s, o);
    int lane = threadIdx.x & 31, wid = threadIdx.x >> 5;
    if (lane == 0) ws[wid] = s;
    __syncthreads();
    if (threadIdx.x == 0) {
        float v = 0.f;
        #pragma unroll
        for (int i = 0; i < 16; i++) v += ws[i];
        out[0] = v * (1.0f / ((float)BATCH * (float)NPTS));
    }
}

extern "C" void kernel_launch(void* const* d_in, const int* in_sizes, int n_in,
                              void* d_out, int out_size) {
    const float* x = (const float*)d_in[0];
    const float* y = (const float*)d_in[1];
    float* out = (float*)d_out;

    dim3 grid(QTILES * SPLITS, BATCH, DIRS);   // 128 x 16 x 2 = 4096 blocks
    chamfer_main_kernel<<<grid, THREADS>>>(x, y);

    chamfer_reduce1_kernel<<<R1BLOCKS, 256>>>();
    chamfer_reduce2_kernel<<<1, 512>>>(out);
}